// round 6
// baseline (speedup 1.0000x reference)
#include <cuda_runtime.h>
#include <cuda_bf16.h>
#include <cstdint>

// ============================================================================
// Problem constants
// ============================================================================
#define B_DIM   256
#define T_DIM   2048
#define K_DIM   64
#define H_DIM   128
#define TILE_T  32
#define N_TILES (T_DIM / TILE_T)   // 64

// Scan: y_t = 0.9*y_{t-1} - 1.25*th_{t-1} + g_t, th = tanh(y), spk = .5th+.5
// g = 2.5*ff - 1.5  (2.5 folded into W, bias' = 2.5b - 1.5)

// ============================================================================
// SMEM layout (bytes)
//   x ring: 2 slots x 9728  (bf16 hi 4608 | x8 2560 | x8lo 2560)
//   W_hi bf16 persistent 18432 (stride 144)
//   W8 / W8lo e4m3 persistent 10240 each (stride 80)
//   ff ring: 3 slots x 16896 ([t][h] stride 132 floats)
// ============================================================================
#define ROWB      144                 // bf16 tile row stride (bytes)
#define ROW8      80                  // fp8 tile row stride (bytes)
#define XSLOT     9728
#define XBUF(s)   ((s) * XSLOT)
#define XOFF8     4608
#define XOFF8LO   7168
#define SMEM_WHI  19456
#define SMEM_W8   37888
#define SMEM_W8LO 48128
#define SMEM_FF   58368
#define FFB(s)    (SMEM_FF + (s) * 16896)
#define FF_STR    132
#define SMEM_TOTAL 109056

// Named barriers: FFREADY(s)=1+s, FFFREE(s)=4+s, XREADY(sx)=7+sx, XFREE(sx)=9+sx
#define BAR_SYNC(id)   asm volatile("bar.sync %0, 256;"   :: "r"(id) : "memory")
#define BAR_ARRIVE(id) asm volatile("bar.arrive %0, 256;" :: "r"(id) : "memory")

// ============================================================================
// Helpers
// ============================================================================
__device__ __forceinline__ uint32_t smem_to_u32(const void* p) {
    uint32_t a;
    asm("{ .reg .u64 t; cvta.to.shared.u64 t, %1; cvt.u32.u64 %0, t; }"
        : "=r"(a) : "l"(p));
    return a;
}
__device__ __forceinline__ float tanhf_approx(float x) {
    float y; asm("tanh.approx.f32 %0, %1;" : "=f"(y) : "f"(x)); return y;
}
__device__ __forceinline__ void ldm_x4(uint32_t* r, uint32_t addr) {
    asm volatile("ldmatrix.sync.aligned.m8n8.x4.shared.b16 {%0,%1,%2,%3}, [%4];"
        : "=r"(r[0]), "=r"(r[1]), "=r"(r[2]), "=r"(r[3]) : "r"(addr));
}
__device__ __forceinline__ void mma_bf16(float* d, const uint32_t* a, const uint32_t* b) {
    asm volatile(
        "mma.sync.aligned.m16n8k16.row.col.f32.bf16.bf16.f32 "
        "{%0,%1,%2,%3},{%4,%5,%6,%7},{%8,%9},{%0,%1,%2,%3};"
        : "+f"(d[0]), "+f"(d[1]), "+f"(d[2]), "+f"(d[3])
        : "r"(a[0]), "r"(a[1]), "r"(a[2]), "r"(a[3]), "r"(b[0]), "r"(b[1]));
}
__device__ __forceinline__ void mma_e4m3(float* d, const uint32_t* a, const uint32_t* b) {
    asm volatile(
        "mma.sync.aligned.m16n8k32.row.col.f32.e4m3.e4m3.f32 "
        "{%0,%1,%2,%3},{%4,%5,%6,%7},{%8,%9},{%0,%1,%2,%3};"
        : "+f"(d[0]), "+f"(d[1]), "+f"(d[2]), "+f"(d[3])
        : "r"(a[0]), "r"(a[1]), "r"(a[2]), "r"(a[3]), "r"(b[0]), "r"(b[1]));
}
__device__ __forceinline__ uint32_t pack_bf16(__nv_bfloat16 a, __nv_bfloat16 b) {
    return ((uint32_t)__bfloat16_as_ushort(b) << 16) | __bfloat16_as_ushort(a);
}
// pack 4 floats -> 4 e4m3 bytes (byte i = value i, little-endian)
__device__ __forceinline__ uint32_t pack_e4m3_4(float x0, float x1, float x2, float x3) {
    uint16_t p01, p23;
    asm("cvt.rn.satfinite.e4m3x2.f32 %0, %1, %2;" : "=h"(p01) : "f"(x1), "f"(x0));
    asm("cvt.rn.satfinite.e4m3x2.f32 %0, %1, %2;" : "=h"(p23) : "f"(x3), "f"(x2));
    return ((uint32_t)p23 << 16) | p01;
}

// consumer: convert one float4 group into x slot (bf16 hi + e4m3 x + e4m3 lo)
__device__ __forceinline__ void convert_to_slot(char* smem, int s, int ct,
                                                const float4* xr) {
#pragma unroll
    for (int q = 0; q < 4; ++q) {
        int idx = ct + (q << 7);
        int row = idx >> 4, c4 = idx & 15;
        float4 v = xr[q];
        __nv_bfloat16 h0 = __float2bfloat16(v.x);
        __nv_bfloat16 h1 = __float2bfloat16(v.y);
        __nv_bfloat16 h2 = __float2bfloat16(v.z);
        __nv_bfloat16 h3 = __float2bfloat16(v.w);
        uint2 hi;
        hi.x = pack_bf16(h0, h1); hi.y = pack_bf16(h2, h3);
        *reinterpret_cast<uint2*>(smem + XBUF(s) + row * ROWB + c4 * 8) = hi;
        // e4m3 of x (for W_lo term)
        *reinterpret_cast<uint32_t*>(smem + XBUF(s) + XOFF8 + row * ROW8 + c4 * 4) =
            pack_e4m3_4(v.x, v.y, v.z, v.w);
        // e4m3 of 256*(x - hi)
        float l0 = (v.x - __bfloat162float(h0)) * 256.0f;
        float l1 = (v.y - __bfloat162float(h1)) * 256.0f;
        float l2 = (v.z - __bfloat162float(h2)) * 256.0f;
        float l3 = (v.w - __bfloat162float(h3)) * 256.0f;
        *reinterpret_cast<uint32_t*>(smem + XBUF(s) + XOFF8LO + row * ROW8 + c4 * 4) =
            pack_e4m3_4(l0, l1, l2, l3);
    }
}

// ============================================================================
// Warp-specialized kernel. 1 CTA / batch, 256 threads.
//   tid 0..127  : consumers — tanh scan (thread = head) + x load/convert
//   tid 128..255: producers — bf16-hi + fp8-correction MMA into ff ring
// ============================================================================
__global__ void __launch_bounds__(256, 2)
snn_encoder_kernel(const float* __restrict__ x, const float* __restrict__ W,
                   const float* __restrict__ bvec, float* __restrict__ out) {
    extern __shared__ char smem[];
    const uint32_t sb = smem_to_u32(smem);
    const int tid = threadIdx.x;
    const int b   = blockIdx.x;
    const float* xb = x + (size_t)b * T_DIM * K_DIM;

    // ---- Cooperative W convert: 2.5*W -> bf16 hi + e4m3(W') + e4m3(256*W'_lo)
    {
        const float4* w4 = reinterpret_cast<const float4*>(W);
#pragma unroll
        for (int q = 0; q < 8; ++q) {
            int idx = tid + (q << 8);            // 2048 float4
            float4 v = __ldg(&w4[idx]);
            v.x *= 2.5f; v.y *= 2.5f; v.z *= 2.5f; v.w *= 2.5f;
            int row = idx >> 4, c4 = idx & 15;
            __nv_bfloat16 h0 = __float2bfloat16(v.x);
            __nv_bfloat16 h1 = __float2bfloat16(v.y);
            __nv_bfloat16 h2 = __float2bfloat16(v.z);
            __nv_bfloat16 h3 = __float2bfloat16(v.w);
            uint2 hi;
            hi.x = pack_bf16(h0, h1); hi.y = pack_bf16(h2, h3);
            *reinterpret_cast<uint2*>(smem + SMEM_WHI + row * ROWB + c4 * 8) = hi;
            *reinterpret_cast<uint32_t*>(smem + SMEM_W8 + row * ROW8 + c4 * 4) =
                pack_e4m3_4(v.x, v.y, v.z, v.w);
            float l0 = (v.x - __bfloat162float(h0)) * 256.0f;
            float l1 = (v.y - __bfloat162float(h1)) * 256.0f;
            float l2 = (v.z - __bfloat162float(h2)) * 256.0f;
            float l3 = (v.w - __bfloat162float(h3)) * 256.0f;
            *reinterpret_cast<uint32_t*>(smem + SMEM_W8LO + row * ROW8 + c4 * 4) =
                pack_e4m3_4(l0, l1, l2, l3);
        }
    }
    __syncthreads();

    if (tid >= 128) {
        // ==================== PRODUCERS ====================
        const int pt   = tid - 128;
        const int lane = pt & 31;
        const int pw   = pt >> 5;                // heads [32pw, 32pw+32)
        const int j    = lane >> 3;

        // bf16 ldmatrix offsets (stride 144 B)
        const uint32_t a_off  = (uint32_t)(((j & 1) * 8 + (lane & 7)) * ROWB + ((j >> 1) * 16));
        const uint32_t b_off  = (uint32_t)(((j >> 1) * 8 + (lane & 7)) * ROWB + ((j & 1) * 16));
        // fp8 ldmatrix offsets (stride 80 B, 16B per 8 k-pairs)
        const uint32_t a8_off = (uint32_t)(((j & 1) * 8 + (lane & 7)) * ROW8 + ((j >> 1) * 16));
        const uint32_t b8_off = (uint32_t)(((j >> 1) * 8 + (lane & 7)) * ROW8 + ((j & 1) * 16));

        const uint32_t aWhi  = sb + SMEM_WHI  + (uint32_t)(pw * 32) * ROWB + a_off;
        const uint32_t aW8   = sb + SMEM_W8   + (uint32_t)(pw * 32) * ROW8 + a8_off;
        const uint32_t aW8lo = sb + SMEM_W8LO + (uint32_t)(pw * 32) * ROW8 + a8_off;

        // bias' = 2.5*b - 1.5 folded into hi-accumulator init
        const int r0 = lane >> 2;
        const int c0 = 2 * (lane & 3);
        float bias0[2], bias1[2];
#pragma unroll
        for (int mt = 0; mt < 2; ++mt) {
            bias0[mt] = fmaf(__ldg(&bvec[pw * 32 + mt * 16 + r0]), 2.5f, -1.5f);
            bias1[mt] = fmaf(__ldg(&bvec[pw * 32 + mt * 16 + r0 + 8]), 2.5f, -1.5f);
        }

        int sf = 0;
        for (int i = 0; i < N_TILES; ++i) {
            const int sx = i & 1;
            BAR_SYNC(7 + sx);                    // wait x tile i converted

            float dh[2][4][4], dl[2][4][4];
#pragma unroll
            for (int mt = 0; mt < 2; ++mt)
#pragma unroll
                for (int nt = 0; nt < 4; ++nt) {
                    dh[mt][nt][0] = bias0[mt]; dh[mt][nt][1] = bias0[mt];
                    dh[mt][nt][2] = bias1[mt]; dh[mt][nt][3] = bias1[mt];
                    dl[mt][nt][0] = 0.f; dl[mt][nt][1] = 0.f;
                    dl[mt][nt][2] = 0.f; dl[mt][nt][3] = 0.f;
                }

            const uint32_t xhi = sb + XBUF(sx) + b_off;
            const uint32_t x8b = sb + XBUF(sx) + XOFF8   + b8_off;
            const uint32_t x8l = sb + XBUF(sx) + XOFF8LO + b8_off;

            // ---- hi term: bf16 x bf16, K=64 (4 ks)
#pragma unroll
            for (int ks = 0; ks < 4; ++ks) {
                uint32_t ah[2][4], bh[2][4];
                ldm_x4(ah[0], aWhi + ks * 32);
                ldm_x4(ah[1], aWhi + 16 * ROWB + ks * 32);
                ldm_x4(bh[0], xhi + ks * 32);
                ldm_x4(bh[1], xhi + 16 * ROWB + ks * 32);
#pragma unroll
                for (int mt = 0; mt < 2; ++mt)
#pragma unroll
                    for (int nt = 0; nt < 4; ++nt)
                        mma_bf16(dh[mt][nt], ah[mt], &bh[nt >> 1][(nt & 1) * 2]);
            }

            // ---- correction terms: e4m3, K=64 (2 K2 chunks of 32)
#pragma unroll
            for (int K2 = 0; K2 < 2; ++K2) {
                uint32_t a8[2][4], a8l[2][4], b8x[2][4], b8lo[2][4];
                ldm_x4(a8[0],  aW8   + K2 * 32);
                ldm_x4(a8[1],  aW8   + 16 * ROW8 + K2 * 32);
                ldm_x4(a8l[0], aW8lo + K2 * 32);
                ldm_x4(a8l[1], aW8lo + 16 * ROW8 + K2 * 32);
                ldm_x4(b8x[0], x8b + K2 * 32);
                ldm_x4(b8x[1], x8b + 16 * ROW8 + K2 * 32);
                ldm_x4(b8lo[0], x8l + K2 * 32);
                ldm_x4(b8lo[1], x8l + 16 * ROW8 + K2 * 32);
#pragma unroll
                for (int mt = 0; mt < 2; ++mt)
#pragma unroll
                    for (int nt = 0; nt < 4; ++nt) {
                        mma_e4m3(dl[mt][nt], a8[mt],  &b8lo[nt >> 1][(nt & 1) * 2]);
                        mma_e4m3(dl[mt][nt], a8l[mt], &b8x[nt >> 1][(nt & 1) * 2]);
                    }
            }
            BAR_ARRIVE(9 + sx);                  // x slot free (LDSM done)

            if (i >= 3) BAR_SYNC(4 + sf);        // wait ff slot free

            // store g = dh + dl/256, layout [t][h] stride 132
            {
                float* ffp = reinterpret_cast<float*>(smem + FFB(sf));
                const int baser = pw * 32 + r0;
#pragma unroll
                for (int mt = 0; mt < 2; ++mt) {
                    const int row = baser + mt * 16;
#pragma unroll
                    for (int nt = 0; nt < 4; ++nt) {
                        const int col = nt * 8 + c0;
                        ffp[col * FF_STR + row] =
                            fmaf(dl[mt][nt][0], 0.00390625f, dh[mt][nt][0]);
                        ffp[(col + 1) * FF_STR + row] =
                            fmaf(dl[mt][nt][1], 0.00390625f, dh[mt][nt][1]);
                        ffp[col * FF_STR + row + 8] =
                            fmaf(dl[mt][nt][2], 0.00390625f, dh[mt][nt][2]);
                        ffp[(col + 1) * FF_STR + row + 8] =
                            fmaf(dl[mt][nt][3], 0.00390625f, dh[mt][nt][3]);
                    }
                }
            }
            BAR_ARRIVE(1 + sf);                  // ff tile ready
            if (++sf == 3) sf = 0;
        }
    } else {
        // ==================== CONSUMERS ====================
        const int h  = tid;
        const int ct = tid;
        float* outp = out + (size_t)b * T_DIM * H_DIM + h;

        // prologue: convert tile 0; prefetch tile 1
        float4 xr[4];
        {
            const float4* x4 = reinterpret_cast<const float4*>(xb);
#pragma unroll
            for (int q = 0; q < 4; ++q) xr[q] = __ldg(&x4[ct + (q << 7)]);
            convert_to_slot(smem, 0, ct, xr);
            BAR_ARRIVE(7 + 0);
            x4 = reinterpret_cast<const float4*>(xb + (size_t)TILE_T * K_DIM);
#pragma unroll
            for (int q = 0; q < 4; ++q) xr[q] = __ldg(&x4[ct + (q << 7)]);
        }

        float z = -1.0f;                         // 0.9*y_{-1} - 1.25*th_{-1}
        int sf = 0;

        for (int i = 0; i < N_TILES; ++i) {
            // convert tile i+1 (regs from last iter), prefetch i+2
            if (i + 1 < N_TILES) {
                const int sn = (i + 1) & 1;
                if (i + 1 >= 2) BAR_SYNC(9 + sn);    // wait slot free
                convert_to_slot(smem, sn, ct, xr);
                BAR_ARRIVE(7 + sn);
            }
            if (i + 2 < N_TILES) {
                const float4* x4 = reinterpret_cast<const float4*>(
                    xb + (size_t)(i + 2) * TILE_T * K_DIM);
#pragma unroll
                for (int q = 0; q < 4; ++q) xr[q] = __ldg(&x4[ct + (q << 7)]);
            }

            BAR_SYNC(1 + sf);                    // wait ff tile i
            const float* fp = reinterpret_cast<const float*>(smem + FFB(sf)) + h;
            float g[TILE_T];
#pragma unroll
            for (int t = 0; t < TILE_T; ++t) g[t] = fp[t * FF_STR];
            BAR_ARRIVE(4 + sf);                  // free ff slot immediately
            if (++sf == 3) sf = 0;

            float* po = outp + (size_t)i * TILE_T * H_DIM;
            float y = z + g[0];
#pragma unroll
            for (int t = 0; t < TILE_T; ++t) {
                float th = tanhf_approx(y);          // MUFU (critical path)
                float gn = (t < TILE_T - 1) ? g[t + 1] : 0.0f;
                float a  = fmaf(0.9f, y, gn);        // parallel with tanh
                y = fmaf(th, -1.25f, a);             // y_{t+1} (or z at t=31)
                float spk = fmaf(th, 0.5f, 0.5f);    // off critical path
                po[(size_t)t * H_DIM] = spk;
            }
            z = y;
        }
    }
}

// ============================================================================
// Launch. Inputs: x [256,2048,64] f32, W [128,64] f32, b [128] f32 -> out f32
// ============================================================================
extern "C" void kernel_launch(void* const* d_in, const int* in_sizes, int n_in,
                              void* d_out, int out_size) {
    const float* x = (const float*)d_in[0];
    const float* W = (const float*)d_in[1];
    const float* b = (const float*)d_in[2];
    float* out = (float*)d_out;

    cudaFuncSetAttribute(snn_encoder_kernel,
                         cudaFuncAttributeMaxDynamicSharedMemorySize, SMEM_TOTAL);
    snn_encoder_kernel<<<B_DIM, 256, SMEM_TOTAL>>>(x, W, b, out);
}

// round 7
// speedup vs baseline: 1.2821x; 1.2821x over previous
#include <cuda_runtime.h>
#include <cuda_bf16.h>
#include <cstdint>

// ============================================================================
// Problem constants
// ============================================================================
#define B_DIM   256
#define T_DIM   2048
#define K_DIM   64
#define H_DIM   128
#define TILE_T  32
#define N_TILES (T_DIM / TILE_T)   // 64

// Scan: y_t = 0.9*y_{t-1} - 1.25*th_{t-1} + g_t, th = tanh(y), spk = .5th+.5
// g = 2.5*ff - 1.5  (2.5 folded into W, bias' = 2.5b - 1.5)

// ============================================================================
// SMEM layout (bytes) — identical to R5 (96.7 KB, 2 CTAs/SM)
//   [0, 27648)        x ring: 3 slots x 9216 (hi 4608 + lo 4608), 32x144B rows
//   [27648, 46080)    W_lo persistent (128 x 144 B)
//   [46080, 96768)    ff ring: 3 slots x 16896 ([t][h] stride 132 floats)
//   W_hi (init only) aliases ff region at 46080.
// ============================================================================
#define WSTR      72
#define ROWB      144
#define XBUF(s)   ((s) * 9216)
#define SMEM_W_LO 27648
#define SMEM_FF   46080
#define FFB(s)    (SMEM_FF + (s) * 16896)
#define FF_STR    132
#define SMEM_W_HI 46080
#define SMEM_TOTAL 96768

// Named barriers (384 threads): FFREADY(s)=1+s, FFFREE(s)=4+s,
// XREADY(s)=7+s, XFREE(s)=10+s, 13 = producer-only (256)
#define BAR_SYNC(id)   asm volatile("bar.sync %0, 384;"   :: "r"(id) : "memory")
#define BAR_ARRIVE(id) asm volatile("bar.arrive %0, 384;" :: "r"(id) : "memory")

// ============================================================================
// Helpers
// ============================================================================
__device__ __forceinline__ uint32_t smem_to_u32(const void* p) {
    uint32_t a;
    asm("{ .reg .u64 t; cvta.to.shared.u64 t, %1; cvt.u32.u64 %0, t; }"
        : "=r"(a) : "l"(p));
    return a;
}
__device__ __forceinline__ float tanhf_approx(float x) {
    float y; asm("tanh.approx.f32 %0, %1;" : "=f"(y) : "f"(x)); return y;
}
__device__ __forceinline__ void ldm_x4(uint32_t* r, uint32_t addr) {
    asm volatile("ldmatrix.sync.aligned.m8n8.x4.shared.b16 {%0,%1,%2,%3}, [%4];"
        : "=r"(r[0]), "=r"(r[1]), "=r"(r[2]), "=r"(r[3]) : "r"(addr));
}
__device__ __forceinline__ void mma_bf16(float* d, const uint32_t* a, const uint32_t* b) {
    asm volatile(
        "mma.sync.aligned.m16n8k16.row.col.f32.bf16.bf16.f32 "
        "{%0,%1,%2,%3},{%4,%5,%6,%7},{%8,%9},{%0,%1,%2,%3};"
        : "+f"(d[0]), "+f"(d[1]), "+f"(d[2]), "+f"(d[3])
        : "r"(a[0]), "r"(a[1]), "r"(a[2]), "r"(a[3]), "r"(b[0]), "r"(b[1]));
}
__device__ __forceinline__ uint32_t pack_bf16(__nv_bfloat16 a, __nv_bfloat16 b) {
    return ((uint32_t)__bfloat16_as_ushort(b) << 16) | __bfloat16_as_ushort(a);
}
__device__ __forceinline__ void cvt_pack(float4 v, uint2& hi, uint2& lo) {
    __nv_bfloat16 h0 = __float2bfloat16(v.x);
    __nv_bfloat16 h1 = __float2bfloat16(v.y);
    __nv_bfloat16 h2 = __float2bfloat16(v.z);
    __nv_bfloat16 h3 = __float2bfloat16(v.w);
    __nv_bfloat16 l0 = __float2bfloat16(v.x - __bfloat162float(h0));
    __nv_bfloat16 l1 = __float2bfloat16(v.y - __bfloat162float(h1));
    __nv_bfloat16 l2 = __float2bfloat16(v.z - __bfloat162float(h2));
    __nv_bfloat16 l3 = __float2bfloat16(v.w - __bfloat162float(h3));
    hi.x = pack_bf16(h0, h1); hi.y = pack_bf16(h2, h3);
    lo.x = pack_bf16(l0, l1); lo.y = pack_bf16(l2, l3);
}

// consumer-side: convert xr regs -> x ring slot s
__device__ __forceinline__ void convert_to_slot(char* smem, int s, int ct,
                                                const float4* xr) {
#pragma unroll
    for (int q = 0; q < 4; ++q) {
        int idx = ct + (q << 7);
        int row = idx >> 4, c4 = idx & 15;
        uint32_t off = (uint32_t)row * ROWB + c4 * 8;
        uint2 hi, lo; cvt_pack(xr[q], hi, lo);
        *reinterpret_cast<uint2*>(smem + XBUF(s) + off)        = hi;
        *reinterpret_cast<uint2*>(smem + XBUF(s) + 4608 + off) = lo;
    }
}

// ============================================================================
// Warp-specialized kernel. 1 CTA / batch, 384 threads.
//   tid 0..127  : consumers — tanh scan (thread = head) + x load/convert
//   tid 128..383: producers — 8 warps, each a 32-head x 16-timestep GEMM slice
// ============================================================================
__global__ void __launch_bounds__(384, 2)
snn_encoder_kernel(const float* __restrict__ x, const float* __restrict__ W,
                   const float* __restrict__ bvec, float* __restrict__ out) {
    extern __shared__ char smem[];
    const uint32_t sb = smem_to_u32(smem);
    const int tid = threadIdx.x;
    const int b   = blockIdx.x;
    const float* xb = x + (size_t)b * T_DIM * K_DIM;

    // ---- Cooperative W convert: (2.5*W) fp32 -> bf16 hi/lo (hi aliases ff)
    {
        const float4* w4 = reinterpret_cast<const float4*>(W);
        for (int idx = tid; idx < 2048; idx += 384) {
            float4 v = __ldg(&w4[idx]);
            v.x *= 2.5f; v.y *= 2.5f; v.z *= 2.5f; v.w *= 2.5f;
            int row = idx >> 4, c4 = idx & 15;
            uint32_t off = (uint32_t)row * ROWB + c4 * 8;
            uint2 hi, lo; cvt_pack(v, hi, lo);
            *reinterpret_cast<uint2*>(smem + SMEM_W_HI + off) = hi;
            *reinterpret_cast<uint2*>(smem + SMEM_W_LO + off) = lo;
        }
    }
    __syncthreads();

    if (tid >= 128) {
        // ==================== PRODUCERS (8 lean warps) ====================
        const int pt   = tid - 128;              // 0..255
        const int lane = pt & 31;
        const int pw   = pt >> 5;                // 0..7
        const int mw   = pw & 3;                 // heads [32mw, 32mw+32)
        const int nw   = pw >> 2;                // timesteps [16nw, 16nw+16)
        const int j    = lane >> 3;

        const uint32_t a_off = (uint32_t)(((j & 1) * 8 + (lane & 7)) * WSTR + ((j >> 1) * 8)) * 2;
        const uint32_t b_off = (uint32_t)(((j >> 1) * 8 + (lane & 7)) * WSTR + ((j & 1) * 8)) * 2;
        const uint32_t aW_lo = sb + SMEM_W_LO + (uint32_t)(mw * 32) * ROWB + a_off;

        // hoist W_hi fragments (ff ring aliases this region afterwards)
        uint32_t Ahi[2][4][4];
        {
            const uint32_t aW_hi = sb + SMEM_W_HI + (uint32_t)(mw * 32) * ROWB + a_off;
#pragma unroll
            for (int mt = 0; mt < 2; ++mt)
#pragma unroll
                for (int ks = 0; ks < 4; ++ks)
                    ldm_x4(Ahi[mt][ks], aW_hi + (uint32_t)mt * 16 * ROWB + ks * 32);
        }
        // all producers done hoisting before any ff STS overwrites W_hi
        asm volatile("bar.sync 13, 256;" ::: "memory");

        // bias' = 2.5*b - 1.5 folded into accumulator init
        const int r0 = lane >> 2;
        const int c0 = 2 * (lane & 3);
        float bias0[2], bias1[2];
#pragma unroll
        for (int mt = 0; mt < 2; ++mt) {
            bias0[mt] = fmaf(__ldg(&bvec[mw * 32 + mt * 16 + r0]), 2.5f, -1.5f);
            bias1[mt] = fmaf(__ldg(&bvec[mw * 32 + mt * 16 + r0 + 8]), 2.5f, -1.5f);
        }

        int sx = 0, sf = 0;
        for (int i = 0; i < N_TILES; ++i) {
            BAR_SYNC(7 + sx);                    // wait x tile i converted

            float d[2][2][4];
#pragma unroll
            for (int mt = 0; mt < 2; ++mt)
#pragma unroll
                for (int nt = 0; nt < 2; ++nt) {
                    d[mt][nt][0] = bias0[mt]; d[mt][nt][1] = bias0[mt];
                    d[mt][nt][2] = bias1[mt]; d[mt][nt][3] = bias1[mt];
                }
            // this warp's 16-timestep slice of the x tile
            const uint32_t bX_hi = sb + XBUF(sx) + (uint32_t)(nw * 16) * ROWB + b_off;
            const uint32_t bX_lo = bX_hi + 4608;
#pragma unroll
            for (int ks = 0; ks < 4; ++ks) {
                uint32_t alo[2][4], bh[4], bl[4];
                ldm_x4(alo[0], aW_lo + ks * 32);
                ldm_x4(alo[1], aW_lo + 16 * ROWB + ks * 32);
                ldm_x4(bh, bX_hi + ks * 32);
                ldm_x4(bl, bX_lo + ks * 32);
#pragma unroll
                for (int mt = 0; mt < 2; ++mt)
#pragma unroll
                    for (int nt = 0; nt < 2; ++nt) {
                        const uint32_t* bhp = &bh[nt * 2];
                        const uint32_t* blp = &bl[nt * 2];
                        mma_bf16(d[mt][nt], Ahi[mt][ks], bhp);
                        mma_bf16(d[mt][nt], Ahi[mt][ks], blp);
                        mma_bf16(d[mt][nt], alo[mt], bhp);
                    }
            }
            BAR_ARRIVE(10 + sx);                 // x slot free (LDSM done)

            if (i >= 3) BAR_SYNC(4 + sf);        // wait ff slot free

            // store ff slice, layout [t][h], stride 132 (conflict-free)
            {
                float* ffp = reinterpret_cast<float*>(smem + FFB(sf));
                const int baser = mw * 32 + r0;
                const int basec = nw * 16 + c0;
#pragma unroll
                for (int mt = 0; mt < 2; ++mt) {
                    const int row = baser + mt * 16;
#pragma unroll
                    for (int nt = 0; nt < 2; ++nt) {
                        const int col = basec + nt * 8;
                        ffp[col * FF_STR + row]           = d[mt][nt][0];
                        ffp[(col + 1) * FF_STR + row]     = d[mt][nt][1];
                        ffp[col * FF_STR + row + 8]       = d[mt][nt][2];
                        ffp[(col + 1) * FF_STR + row + 8] = d[mt][nt][3];
                    }
                }
            }
            BAR_ARRIVE(1 + sf);                  // ff tile ready

            if (++sx == 3) sx = 0;
            if (++sf == 3) sf = 0;
        }
    } else {
        // ==================== CONSUMERS (scan + x feed) ====================
        const int h  = tid;
        const int ct = tid;
        float* outp = out + (size_t)b * T_DIM * H_DIM + h;

        // prologue: convert x tiles 0,1 into slots 0,1; prefetch tile 2
        float4 xr[4];
        {
            const float4* x4 = reinterpret_cast<const float4*>(xb);
#pragma unroll
            for (int q = 0; q < 4; ++q) xr[q] = __ldg(&x4[ct + (q << 7)]);
            convert_to_slot(smem, 0, ct, xr);
            BAR_ARRIVE(7 + 0);
            x4 = reinterpret_cast<const float4*>(xb + (size_t)TILE_T * K_DIM);
#pragma unroll
            for (int q = 0; q < 4; ++q) xr[q] = __ldg(&x4[ct + (q << 7)]);
            convert_to_slot(smem, 1, ct, xr);
            BAR_ARRIVE(7 + 1);
            x4 = reinterpret_cast<const float4*>(xb + (size_t)2 * TILE_T * K_DIM);
#pragma unroll
            for (int q = 0; q < 4; ++q) xr[q] = __ldg(&x4[ct + (q << 7)]);
        }

        // scan state: z = 0.9*y_{-1} - 1.25*th_{-1} = -1.0 (mem=0, spk=0)
        float z = -1.0f;
        int sf = 0, sx = 2;                      // next convert slot = tile 2

        for (int i = 0; i < N_TILES; ++i) {
            // convert tile i+2 (regs loaded last iter), then prefetch i+3
            if (i + 2 < N_TILES) {
                if (i + 2 >= 3) BAR_SYNC(10 + sx);
                convert_to_slot(smem, sx, ct, xr);
                BAR_ARRIVE(7 + sx);
                if (++sx == 3) sx = 0;
            }
            if (i + 3 < N_TILES) {
                const float4* x4 = reinterpret_cast<const float4*>(
                    xb + (size_t)(i + 3) * TILE_T * K_DIM);
#pragma unroll
                for (int q = 0; q < 4; ++q) xr[q] = __ldg(&x4[ct + (q << 7)]);
            }

            BAR_SYNC(1 + sf);                    // wait ff tile i
            const float* fp = reinterpret_cast<const float*>(smem + FFB(sf)) + h;
            float g[TILE_T];
#pragma unroll
            for (int t = 0; t < TILE_T; ++t) g[t] = fp[t * FF_STR];
            BAR_ARRIVE(4 + sf);                  // free ff slot immediately
            if (++sf == 3) sf = 0;

            float* po = outp + (size_t)i * TILE_T * H_DIM;
            float y = z + g[0];
#pragma unroll
            for (int t = 0; t < TILE_T; ++t) {
                float th = tanhf_approx(y);          // MUFU (critical path)
                float gn = (t < TILE_T - 1) ? g[t + 1] : 0.0f;
                float a  = fmaf(0.9f, y, gn);        // parallel with tanh
                y = fmaf(th, -1.25f, a);             // y_{t+1} (or z at t=31)
                float spk = fmaf(th, 0.5f, 0.5f);    // off critical path
                po[(size_t)t * H_DIM] = spk;
            }
            z = y;                               // carry partial to next tile
        }
    }
}

// ============================================================================
// Launch. Inputs: x [256,2048,64] f32, W [128,64] f32, b [128] f32 -> out f32
// ============================================================================
extern "C" void kernel_launch(void* const* d_in, const int* in_sizes, int n_in,
                              void* d_out, int out_size) {
    const float* x = (const float*)d_in[0];
    const float* W = (const float*)d_in[1];
    const float* b = (const float*)d_in[2];
    float* out = (float*)d_out;

    cudaFuncSetAttribute(snn_encoder_kernel,
                         cudaFuncAttributeMaxDynamicSharedMemorySize, SMEM_TOTAL);
    snn_encoder_kernel<<<B_DIM, 384, SMEM_TOTAL>>>(x, W, b, out);
}